// round 9
// baseline (speedup 1.0000x reference)
#include <cuda_runtime.h>
#include <cstdint>

#define NUM_CLASSES 17929
#define BATCH       512
#define NUM_MODELS  16
#define HIDDEN      4

#define TPB         256
#define CPT         128            // classes per CTA (2 threads/class)
#define BT          2              // batch rows per tile
#define RPC         128            // batch rows per CTA  (grid.y = 4)
#define NT          (RPC / BT)     // 64 tiles per CTA
#define STAGES      3
#define PLANES      (NUM_MODELS * BT)            // 32
#define PADW        132                          // 128 + shift(<=3) + pad; 528B stride (16B aligned)
#define HALF_OFF    16                           // +16 floats for planes q>=16 (bank de-conflict)
#define STAGE_FLOATS (PLANES * PADW + HALF_OFF)  // 4240
#define STAGE_BYTES  (STAGE_FLOATS * 4)          // 16960
#define SMEM_BYTES   (STAGES * STAGE_BYTES)      // 50880 -> 4 CTAs/SM

__device__ __forceinline__ void cp_async16(uint32_t dst, const float* src) {
    asm volatile("cp.async.cg.shared.global [%0], [%1], 16;\n" :: "r"(dst), "l"(src));
}
__device__ __forceinline__ void cp_async4(uint32_t dst, const float* src) {
    asm volatile("cp.async.ca.shared.global [%0], [%1], 4;\n" :: "r"(dst), "l"(src));
}
__device__ __forceinline__ void cp_commit() {
    asm volatile("cp.async.commit_group;\n" ::: "memory");
}
__device__ __forceinline__ void cp_wait1() {
    asm volatile("cp.async.wait_group 1;\n" ::: "memory");
}
__device__ __forceinline__ void cp_wait0() {
    asm volatile("cp.async.wait_group 0;\n" ::: "memory");
}

extern __shared__ float smem[];    // [STAGES][PLANES][PADW] (+HALF_OFF for q>=16)

__global__ void __launch_bounds__(TPB, 4)
family_mlp_kernel(const float* __restrict__ x,     // [M, B, C]
                  const float* __restrict__ W1,    // [C, H, M]
                  const float* __restrict__ b1,    // [C, H]
                  const float* __restrict__ W2,    // [C, H]
                  const float* __restrict__ b2,    // [C]
                  float* __restrict__ out)         // [B, C]
{
    const int tid  = threadIdx.x;
    const int ci   = tid >> 1;     // class index within tile
    const int half = tid & 1;      // which 8 models this thread owns
    int c0 = blockIdx.x * CPT;
    if (c0 > NUM_CLASSES - CPT) c0 = NUM_CLASSES - CPT;   // overlap last block
    const int c04 = c0 & 3;
    const int c   = c0 + ci;
    const int r0  = blockIdx.y * RPC;

    // ---- this thread's 8 models' weights (32 regs) ----
    float w1[HIDDEN][8];
    {
        const float* Wb = W1 + (size_t)c * (HIDDEN * NUM_MODELS) + half * 8;
        #pragma unroll
        for (int h = 0; h < HIDDEN; ++h) {
            float4 va = __ldg(reinterpret_cast<const float4*>(Wb + h * NUM_MODELS));
            float4 vb = __ldg(reinterpret_cast<const float4*>(Wb + h * NUM_MODELS + 4));
            w1[h][0] = va.x; w1[h][1] = va.y; w1[h][2] = va.z; w1[h][3] = va.w;
            w1[h][4] = vb.x; w1[h][5] = vb.y; w1[h][6] = vb.z; w1[h][7] = vb.w;
        }
    }
    const float4 bb1 = __ldg(reinterpret_cast<const float4*>(b1) + c);
    const float4 ww2 = __ldg(reinterpret_cast<const float4*>(W2) + c);
    const float  bb2 = __ldg(b2 + c);

    // half 0 seeds the hidden bias so the pairwise sum counts it once
    const float h0i = half ? 0.0f : bb1.x;
    const float h1i = half ? 0.0f : bb1.y;
    const float h2i = half ? 0.0f : bb1.z;
    const float h3i = half ? 0.0f : bb1.w;

    const size_t plane = (size_t)BATCH * NUM_CLASSES;
    float* obase = out + (size_t)r0 * NUM_CLASSES + c;

    uint32_t sbase;
    asm("{ .reg .u64 t; cvta.to.shared.u64 t, %1; cvt.u32.u64 %0, t; }"
        : "=r"(sbase) : "l"(smem));

    const int lane32 = tid & 31;    // covers one plane's 32 float4 copies
    const int pgrp   = tid >> 5;    // 0..7: plane group

    // issue one tile's copies: 32 planes x 32 float4 (+ <=3 tail scalars/plane)
    auto issue_tile = [&](int t) {
        const int stage = t % STAGES;
        const uint32_t s0 = sbase + stage * STAGE_BYTES;
        #pragma unroll
        for (int it = 0; it < PLANES / 8; ++it) {
            const int q = pgrp + (it << 3);         // 0..31  (q = m*2 + b)
            const int m = q >> 1, b = q & 1;
            const int a = (c04 + 2 * t + b) & 3;    // misalignment in elements
            const float* g = x + (size_t)m * plane
                               + (size_t)(r0 + 2 * t + b) * NUM_CLASSES + c0;
            // planes q>=16 shifted +64B so odd/even lanes hit disjoint bank halves
            const uint32_t dplane = s0 + q * (PADW * 4) + ((q >= 16) ? (HALF_OFF * 4) : 0);
            cp_async16(dplane + lane32 * 16, (g - a) + lane32 * 4);
            if (lane32 < a)   // tail classes -> slots CPT..CPT+a-1
                cp_async4(dplane + (CPT + lane32) * 4, g + CPT - a + lane32);
        }
        cp_commit();
    };

    // ---- prologue ----
    issue_tile(0);
    issue_tile(1);

    #pragma unroll 1
    for (int t = 0; t < NT; ++t) {
        if (t == NT - 1) cp_wait0(); else cp_wait1();
        __syncthreads();   // copies of tile t visible; compute of t-1 done everywhere
        if (t + STAGES - 1 < NT) issue_tile(t + STAGES - 1);

        const int stage = t % STAGES;
        const float* sb = smem + stage * STAGE_FLOATS;

        #pragma unroll
        for (int b = 0; b < BT; ++b) {
            const int a = (c04 + 2 * t + b) & 3;
            // q = (half*8 + k)*2 + b -> base = q*PADW + half*HALF_OFF + ci + a
            const float* buf = sb + (size_t)(16 * half + b) * PADW
                                  + half * HALF_OFF + ci + a;

            float h0 = h0i, h1 = h1i, h2 = h2i, h3 = h3i;
            #pragma unroll
            for (int k = 0; k < 8; ++k) {
                const float v = buf[2 * k * PADW];
                h0 = fmaf(v, w1[0][k], h0);
                h1 = fmaf(v, w1[1][k], h1);
                h2 = fmaf(v, w1[2][k], h2);
                h3 = fmaf(v, w1[3][k], h3);
            }
            // combine the two model halves (partner lane = tid^1)
            h0 += __shfl_xor_sync(0xFFFFFFFFu, h0, 1);
            h1 += __shfl_xor_sync(0xFFFFFFFFu, h1, 1);
            h2 += __shfl_xor_sync(0xFFFFFFFFu, h2, 1);
            h3 += __shfl_xor_sync(0xFFFFFFFFu, h3, 1);

            if (half == 0) {
                float acc = bb2;
                acc = fmaf(fmaxf(h0, 0.0f), ww2.x, acc);
                acc = fmaf(fmaxf(h1, 0.0f), ww2.y, acc);
                acc = fmaf(fmaxf(h2, 0.0f), ww2.z, acc);
                acc = fmaf(fmaxf(h3, 0.0f), ww2.w, acc);
                __stcs(obase + (size_t)(2 * t + b) * NUM_CLASSES, acc);
            }
        }
    }
}

extern "C" void kernel_launch(void* const* d_in, const int* in_sizes, int n_in,
                              void* d_out, int out_size)
{
    const float* x  = (const float*)d_in[0];   // [16, 512, 17929]
    const float* W1 = (const float*)d_in[1];   // [17929, 4, 16]
    const float* b1 = (const float*)d_in[2];   // [17929, 4]
    const float* W2 = (const float*)d_in[3];   // [17929, 4]
    const float* b2 = (const float*)d_in[4];   // [17929]
    float* out = (float*)d_out;                // [512, 17929]

    cudaFuncSetAttribute(family_mlp_kernel,
                         cudaFuncAttributeMaxDynamicSharedMemorySize, SMEM_BYTES);

    dim3 grid((NUM_CLASSES + CPT - 1) / CPT, BATCH / RPC);   // 141 x 4 = 564 CTAs
    family_mlp_kernel<<<grid, TPB, SMEM_BYTES>>>(x, W1, b1, W2, b2, out);
}